// round 7
// baseline (speedup 1.0000x reference)
#include <cuda_runtime.h>

#define N_COLS    22
#define N_PAIRS   231
#define EMB_NUM   12
#define DIM       64
#define BATCH     4096
#define NFF       (EMB_NUM * EMB_NUM)   // 144
#define ROWS_TILE 32
#define N_TILES   (BATCH / ROWS_TILE)   // 128
#define GRID      148                   // one CTA per SM -> single wave, spin-safe
#define THREADS   512
#define WARPS     16
#define MAIN_ITERS 15                   // ceil(231/16)

// Pair-contribution table: T[p][fi][fj] -> (out0, out1)
__device__ float2   g_T[N_PAIRS * NFF];
__device__ unsigned g_bar;              // monotonic epoch barrier counter

__global__ __launch_bounds__(THREADS) void nasp_fused_kernel(
        const int*   __restrict__ feats,
        const float* __restrict__ tables,
        const float* __restrict__ Ws,    // (231,4,2,64)
        const float* __restrict__ Wc,    // (231,2,128)
        const float* __restrict__ aw,    // (231,5)
        float*       __restrict__ out) {
    __shared__ union {
        struct {                          // phase 1
            float A[8 * DIM];             // a_k * W_small[p][k][o][d], row k*2+o
            float C[4 * DIM];             // a_4 * W_concat[p][o][half], row o*2+half
            float P[EMB_NUM * DIM];       // tables[i][*][:]
            float Q[EMB_NUM * DIM];       // tables[j][*][:]
        } prep;
        struct {                          // phase 2
            int    feat[N_COLS][ROWS_TILE];
            int    ij[N_PAIRS + 1];
            float2 part[WARPS][ROWS_TILE];
        } mn;
    } sm;

    int tid  = threadIdx.x;
    int warp = tid >> 5, lane = tid & 31;

    // ---------------- Phase 1: build g_T (pairs strided over CTAs) ----------
    for (int p = blockIdx.x; p < N_PAIRS; p += GRID) {
        // triu_indices(22, k=1) row-major unrank
        int i = 0, rem = p, span = N_COLS - 1;
        while (rem >= span) { rem -= span; i++; span--; }
        int j = i + 1 + rem;

        // Stage weights with arch_weights folded in (512 threads, exact fit)
        sm.prep.A[tid] = Ws[p * 512 + tid] * aw[p * 5 + (tid >> 7)];
        if (tid < 256) sm.prep.C[tid] = Wc[p * 256 + tid] * aw[p * 5 + 4];
        for (int idx = tid; idx < EMB_NUM * DIM; idx += THREADS) {
            sm.prep.P[idx] = tables[(i * EMB_NUM) * DIM + idx];
            sm.prep.Q[idx] = tables[(j * EMB_NUM) * DIM + idx];
        }
        __syncthreads();

        for (int c = warp; c < NFF; c += WARPS) {
            int fi = c / EMB_NUM;
            int fj = c - fi * EMB_NUM;
            float acc0 = 0.f, acc1 = 0.f;
#pragma unroll
            for (int r = 0; r < 2; r++) {
                int d = lane + 32 * r;
                float P = sm.prep.P[fi * DIM + d], Q = sm.prep.Q[fj * DIM + d];
                float s   = P + Q;
                float m   = P * Q;
                float mx  = fmaxf(P, Q);
                float mnv = fminf(P, Q);
                acc0 += s * sm.prep.A[0 * DIM + d] + m   * sm.prep.A[2 * DIM + d]
                      + mx * sm.prep.A[4 * DIM + d] + mnv * sm.prep.A[6 * DIM + d]
                      + P * sm.prep.C[0 * DIM + d] + Q * sm.prep.C[1 * DIM + d];
                acc1 += s * sm.prep.A[1 * DIM + d] + m   * sm.prep.A[3 * DIM + d]
                      + mx * sm.prep.A[5 * DIM + d] + mnv * sm.prep.A[7 * DIM + d]
                      + P * sm.prep.C[2 * DIM + d] + Q * sm.prep.C[3 * DIM + d];
            }
#pragma unroll
            for (int off = 16; off; off >>= 1) {
                acc0 += __shfl_xor_sync(0xffffffffu, acc0, off);
                acc1 += __shfl_xor_sync(0xffffffffu, acc1, off);
            }
            if (lane == 0) g_T[p * NFF + c] = make_float2(acc0, acc1);
        }
        __syncthreads();   // protect smem before restaging next pair
    }

    // ---------------- Grid barrier (monotonic epoch, replay-safe) -----------
    __syncthreads();
    if (tid == 0) {
        __threadfence();                          // release: publish g_T
        unsigned old    = atomicAdd(&g_bar, 1u);
        unsigned target = (old / GRID + 1u) * GRID;
        while (*(volatile unsigned*)&g_bar < target) __nanosleep(64);
        __threadfence();                          // acquire: order g_T reads after spin
    }
    __syncthreads();

    // ---------------- Phase 2: batch gather (tiles 0..127 on CTAs 0..127) ---
    int tile = blockIdx.x;
    if (tile >= N_TILES) return;
    int base = tile * ROWS_TILE;

    for (int idx = tid; idx < ROWS_TILE * N_COLS; idx += THREADS) {
        int r = idx / N_COLS, c = idx - r * N_COLS;
        sm.mn.feat[c][r] = feats[(base + r) * N_COLS + c];
    }
    if (tid <= N_PAIRS) {                        // unrank all pairs locally
        int p = tid;
        int i = 0, rem = p, span = N_COLS - 1;
        while (rem >= span) { rem -= span; i++; span--; }
        sm.mn.ij[tid] = (i << 5) | (i + 1 + rem); // tid==231 -> harmless dummy
    }
    __syncthreads();

    float a0 = 0.f, a1 = 0.f;
#pragma unroll
    for (int t = 0; t < MAIN_ITERS; t++) {
        int p = warp + WARPS * t;
        if (p < N_PAIRS) {
            int ij = sm.mn.ij[p];                // uniform -> smem broadcast
            int fi = sm.mn.feat[ij >> 5][lane];  // conflict-free LDS
            int fj = sm.mn.feat[ij & 31][lane];
            float2 v = __ldg(&g_T[p * NFF + fi * EMB_NUM + fj]);
            a0 += v.x;
            a1 += v.y;
        }
    }
    sm.mn.part[warp][lane] = make_float2(a0, a1);
    __syncthreads();

    if (tid < ROWS_TILE * 2) {
        int r = tid >> 1, o = tid & 1;
        float s = 0.f;
#pragma unroll
        for (int ww = 0; ww < WARPS; ww++)
            s += o ? sm.mn.part[ww][r].y : sm.mn.part[ww][r].x;
        out[(base + r) * 2 + o] = s;
    }
}

extern "C" void kernel_launch(void* const* d_in, const int* in_sizes, int n_in,
                              void* d_out, int out_size) {
    const int*   feats  = (const int*)  d_in[0];
    const float* tables = (const float*)d_in[1];
    const float* Ws     = (const float*)d_in[2];
    const float* Wc     = (const float*)d_in[3];
    const float* aw     = (const float*)d_in[4];
    float* out = (float*)d_out;

    nasp_fused_kernel<<<GRID, THREADS>>>(feats, tables, Ws, Wc, aw, out);
}